// round 15
// baseline (speedup 1.0000x reference)
#include <cuda_runtime.h>
#include <cuda_bf16.h>

#define N_SEQ   256
#define M_GENES 2000
#define D_DIM   128
#define N_NUC   4
#define MT      8                     // genes per tile
#define NTT     32                    // sequences per tile
#define M_TILES (M_GENES / MT)        // 250
#define N_TILES (N_SEQ / NTT)         // 8
#define SEG_ROWS (MT * N_NUC)         // 32 table rows per tile

// Single fused kernel: tile = 32 sequences x 8 genes.
// Phase 1: load + normalize 32 table rows (16 KB) into smem (one batch).
// Phase 2: gather from smem, write 4 KB contiguous chunks per (warp, n).
// __launch_bounds__(256, 6): cap regs at 42 so 6 blocks/SM fit (was 5).
__global__ void __launch_bounds__(256, 6) fused_tile_kernel(
        const int* __restrict__ seq,
        const float* __restrict__ emb,
        float* __restrict__ out) {
    __shared__ float s_tab[SEG_ROWS * D_DIM];   // 16 KB
    __shared__ int   s_idx[NTT * MT];           // 1 KB

    const unsigned int mt = blockIdx.x % M_TILES;   // adjacent blocks -> adjacent m
    const unsigned int nt = blockIdx.x / M_TILES;
    const unsigned int m0 = mt * MT;
    const unsigned int n0 = nt * NTT;
    const unsigned int tid  = threadIdx.x;
    const unsigned int warp = tid >> 5;
    const unsigned int lane = tid & 31u;

    // ---- Indices: 256 ints, one per thread (tid = n_local*MT + m_local) ----
    {
        int n = tid / MT, m = tid % MT;
        s_idx[tid] = __ldg(seq + (size_t)(n0 + n) * M_GENES + m0 + m);
    }

    // ---- Table: 32 contiguous rows from m0*4. Warp w owns rows [w*4, w*4+4):
    //      one batch of MLP=4 loads, 4 interleaved warp allreduces. ----
    {
        float4 v[4];
        float  ss[4];
        #pragma unroll
        for (int j = 0; j < 4; j++) {
            int r = warp * 4 + j;
            v[j] = __ldg(reinterpret_cast<const float4*>(
                        emb + ((size_t)m0 * N_NUC + r) * D_DIM) + lane);
        }
        #pragma unroll
        for (int j = 0; j < 4; j++)
            ss[j] = v[j].x * v[j].x + v[j].y * v[j].y
                  + v[j].z * v[j].z + v[j].w * v[j].w;
        #pragma unroll
        for (int o = 16; o > 0; o >>= 1) {
            #pragma unroll
            for (int j = 0; j < 4; j++)
                ss[j] += __shfl_xor_sync(0xffffffffu, ss[j], o);
        }
        #pragma unroll
        for (int j = 0; j < 4; j++) {
            int r = warp * 4 + j;
            float inv = 1.0f / fmaxf(sqrtf(ss[j]), 1e-12f);
            v[j].x *= inv; v[j].y *= inv; v[j].z *= inv; v[j].w *= inv;
            reinterpret_cast<float4*>(s_tab + (size_t)r * D_DIM)[lane] = v[j];
        }
    }
    __syncthreads();

    // ---- Emit: warp w serves n-locals {w, w+8, w+16, w+24}; per n,
    //      8 m-consecutive rows = 4 KB contiguous.
    //      Batch: 8 conflict-free LDS.128, then 8 streaming STG.128. ----
    #pragma unroll
    for (int nn = warp; nn < NTT; nn += 8) {
        float4* dst = reinterpret_cast<float4*>(
            out + ((size_t)(n0 + nn) * M_GENES + m0) * D_DIM) + lane;
        const int* idx = s_idx + nn * MT;
        float4 v[MT];
        #pragma unroll
        for (int m = 0; m < MT; m++) {
            int g = idx[m];                        // uniform -> LDS broadcast
            v[m] = reinterpret_cast<const float4*>(
                       s_tab + ((size_t)(m * N_NUC + g)) * D_DIM)[lane];
        }
        #pragma unroll
        for (int m = 0; m < MT; m++)
            __stcs(dst + (size_t)m * 32, v[m]);
    }
}

extern "C" void kernel_launch(void* const* d_in, const int* in_sizes, int n_in,
                              void* d_out, int out_size) {
    const int*   gene_seq = (const int*)d_in[0];     // (256, 2000) int32
    const float* emb      = (const float*)d_in[1];   // (2000, 4, 128) f32
    float*       out      = (float*)d_out;           // (256, 2000, 128) f32

    fused_tile_kernel<<<M_TILES * N_TILES, 256>>>(gene_seq, emb, out);
}